// round 15
// baseline (speedup 1.0000x reference)
#include <cuda_runtime.h>

#define HID    400
#define SEQ    8192
#define DEPTH  32
#define ROW    (DEPTH * HID)       // 12800 floats per timestep slab
#define TOPF4  (HID / 4)           // 100 float4 in row 0
#define TPB    128
#define WPB    (TPB / 32)          // 4 warps (= timesteps) per block
#define NCH    4                   // pipeline chunks
#define SLABS_PER_CH (SEQ / NCH)   // 2048 slabs per chunk

// Per-timestep scalar: s_t = softmax(h_t @ W^T + b)[0] * sigmoid(h_t @ D)
__device__ float g_scalar[SEQ];

// One warp per timestep: 4 dot products of length 400, butterfly reduce,
// lane 0 stores the scalar. Overlaps the first chunk memsets.
__global__ void __launch_bounds__(TPB)
compute_kernel(const float* __restrict__ hid,
               const float* __restrict__ W,
               const float* __restrict__ b,
               const float* __restrict__ D)
{
    const int warp = threadIdx.x >> 5;
    const int lane = threadIdx.x & 31;
    const int t    = blockIdx.x * WPB + warp;

    const float4* h4 = reinterpret_cast<const float4*>(hid + (size_t)t * HID);
    const float4* W4 = reinterpret_cast<const float4*>(W);
    const float4* D4 = reinterpret_cast<const float4*>(D);

    float a0 = 0.f, a1 = 0.f, a2 = 0.f, ad = 0.f;
    #pragma unroll
    for (int k = 0; k < 4; k++) {
        int i = lane + (k << 5);
        if (i < TOPF4) {
            float4 x  = h4[i];
            float4 w0 = W4[i];
            float4 w1 = W4[TOPF4 + i];
            float4 w2 = W4[2 * TOPF4 + i];
            float4 dd = D4[i];
            a0 += x.x * w0.x + x.y * w0.y + x.z * w0.z + x.w * w0.w;
            a1 += x.x * w1.x + x.y * w1.y + x.z * w1.z + x.w * w1.w;
            a2 += x.x * w2.x + x.y * w2.y + x.z * w2.z + x.w * w2.w;
            ad += x.x * dd.x + x.y * dd.y + x.z * dd.z + x.w * dd.w;
        }
    }

    #pragma unroll
    for (int o = 16; o > 0; o >>= 1) {
        a0 += __shfl_xor_sync(0xffffffffu, a0, o);
        a1 += __shfl_xor_sync(0xffffffffu, a1, o);
        a2 += __shfl_xor_sync(0xffffffffu, a2, o);
        ad += __shfl_xor_sync(0xffffffffu, ad, o);
    }

    if (lane == 0) {
        float l0 = a0 + b[0], l1 = a1 + b[1], l2 = a2 + b[2];
        float m  = fmaxf(l0, fmaxf(l1, l2));
        float e0 = __expf(l0 - m);
        float e1 = __expf(l1 - m);
        float e2 = __expf(l2 - m);
        float p  = e0 / (e0 + e1 + e2);
        float v  = 1.f / (1.f + __expf(-ad));
        g_scalar[t] = p * v;
    }
}

// One warp per slab: broadcast g_scalar[t] into row 0 of slab t within chunk.
__global__ void __launch_bounds__(TPB)
scatter_kernel(float* __restrict__ out, int t0)
{
    const int warp = threadIdx.x >> 5;
    const int lane = threadIdx.x & 31;
    const int t    = t0 + blockIdx.x * WPB + warp;

    const float  s  = g_scalar[t];
    const float4 sv = make_float4(s, s, s, s);
    float4* o = reinterpret_cast<float4*>(out + (size_t)t * ROW);
    #pragma unroll
    for (int k = 0; k < 4; k++) {
        int i = lane + (k << 5);
        if (i < TOPF4) o[i] = sv;
    }
}

namespace {
struct Ctx {
    cudaStream_t sM, sK, sS;         // memset / compute / scatter streams
    cudaEvent_t  ev_fork, ev_c, ev_m[NCH], ev_s;
    Ctx() {
        cudaStreamCreateWithFlags(&sM, cudaStreamNonBlocking);
        cudaStreamCreateWithFlags(&sK, cudaStreamNonBlocking);
        cudaStreamCreateWithFlags(&sS, cudaStreamNonBlocking);
        cudaEventCreateWithFlags(&ev_fork, cudaEventDisableTiming);
        cudaEventCreateWithFlags(&ev_c,    cudaEventDisableTiming);
        for (int i = 0; i < NCH; i++)
            cudaEventCreateWithFlags(&ev_m[i], cudaEventDisableTiming);
        cudaEventCreateWithFlags(&ev_s,    cudaEventDisableTiming);
    }
};
Ctx ctx;  // host-side stream/event resources only (no device allocations)
}

extern "C" void kernel_launch(void* const* d_in, const int* in_sizes, int n_in,
                              void* d_out, int out_size)
{
    const float* hid = (const float*)d_in[0];   // (1, 8192, 400)
    const float* W   = (const float*)d_in[1];   // (3, 400)
    const float* b   = (const float*)d_in[2];   // (3,)
    const float* D   = (const float*)d_in[3];   // (1, 400)
    float* out = (float*)d_out;                 // (1, 8192, 32, 400)

    cudaEventRecord(ctx.ev_fork, 0);
    cudaStreamWaitEvent(ctx.sM, ctx.ev_fork, 0);
    cudaStreamWaitEvent(ctx.sK, ctx.ev_fork, 0);

    // Compute all per-timestep scalars (overlaps the first chunk memsets).
    compute_kernel<<<SEQ / WPB, TPB, 0, ctx.sK>>>(hid, W, b, D);
    cudaEventRecord(ctx.ev_c, ctx.sK);

    // Flat memsets of contiguous 105 MB chunks (fast fill path), pipelined.
    const size_t chBytes = (size_t)SLABS_PER_CH * ROW * sizeof(float);
    for (int c = 0; c < NCH; c++) {
        cudaMemsetAsync(out + (size_t)c * SLABS_PER_CH * ROW, 0, chBytes, ctx.sM);
        cudaEventRecord(ctx.ev_m[c], ctx.sM);
    }

    // Scatter row 0 of chunk c once its memset (and the compute) finished.
    cudaStreamWaitEvent(ctx.sS, ctx.ev_c, 0);
    for (int c = 0; c < NCH; c++) {
        cudaStreamWaitEvent(ctx.sS, ctx.ev_m[c], 0);
        scatter_kernel<<<SLABS_PER_CH / WPB, TPB, 0, ctx.sS>>>(out, c * SLABS_PER_CH);
    }
    cudaEventRecord(ctx.ev_s, ctx.sS);

    // Join into the capture stream.
    cudaStreamWaitEvent(0, ctx.ev_s, 0);
}

// round 16
// speedup vs baseline: 1.0755x; 1.0755x over previous
#include <cuda_runtime.h>

#define HID    400
#define SEQ    8192
#define DEPTH  32
#define ROWF4  (DEPTH * HID / 4)   // 3200 float4 per timestep slab
#define TOPF4  (HID / 4)           // 100 float4 in row 0
#define TPB    256
#define SPB    8                   // slabs (timesteps) per block
#define F4PB   (SPB * ROWF4)       // 25600 float4 per block
#define NITER  (F4PB / TPB)        // 100 store iterations per thread

__global__ void __launch_bounds__(TPB, 7)
stack_kernel(const float* __restrict__ hid,
             const float* __restrict__ W,
             const float* __restrict__ b,
             const float* __restrict__ D,
             float* __restrict__ out)
{
    const int tid  = threadIdx.x;
    const int warp = tid >> 5;
    const int lane = tid & 31;
    const int t0   = blockIdx.x * SPB;

    // ---- Phase 1: warp w computes the scalar for slab t0 + w ----
    const int t = t0 + warp;
    const float4* h4 = reinterpret_cast<const float4*>(hid + (size_t)t * HID);
    const float4* W4 = reinterpret_cast<const float4*>(W);
    const float4* D4 = reinterpret_cast<const float4*>(D);

    float a0 = 0.f, a1 = 0.f, a2 = 0.f, ad = 0.f;
    #pragma unroll
    for (int k = 0; k < 4; k++) {
        int i = lane + (k << 5);
        if (i < TOPF4) {
            float4 x  = h4[i];
            float4 w0 = W4[i];
            float4 w1 = W4[TOPF4 + i];
            float4 w2 = W4[2 * TOPF4 + i];
            float4 dd = D4[i];
            a0 += x.x * w0.x + x.y * w0.y + x.z * w0.z + x.w * w0.w;
            a1 += x.x * w1.x + x.y * w1.y + x.z * w1.z + x.w * w1.w;
            a2 += x.x * w2.x + x.y * w2.y + x.z * w2.z + x.w * w2.w;
            ad += x.x * dd.x + x.y * dd.y + x.z * dd.z + x.w * dd.w;
        }
    }

    #pragma unroll
    for (int o = 16; o > 0; o >>= 1) {
        a0 += __shfl_xor_sync(0xffffffffu, a0, o);
        a1 += __shfl_xor_sync(0xffffffffu, a1, o);
        a2 += __shfl_xor_sync(0xffffffffu, a2, o);
        ad += __shfl_xor_sync(0xffffffffu, ad, o);
    }

    __shared__ float s_sh[SPB];
    if (lane == 0) {
        float l0 = a0 + b[0], l1 = a1 + b[1], l2 = a2 + b[2];
        float m  = fmaxf(l0, fmaxf(l1, l2));
        float e0 = __expf(l0 - m);
        float e1 = __expf(l1 - m);
        float e2 = __expf(l2 - m);
        float p  = e0 / (e0 + e1 + e2);
        float v  = 1.f / (1.f + __expf(-ad));
        s_sh[warp] = p * v;
    }
    __syncthreads();

    // ---- Phase 2: all 8 warps stream the block's 8 slabs (400 KB contiguous) ----
    // float4 index idx in [0, 25600): slab = idx / 3200, in-slab = idx % 3200.
    // in-slab < 100 -> scalar row, else zero. Streaming stores (.cs) keep the
    // dead write data out of L2's working set.
    float4* base = reinterpret_cast<float4*>(out) + (size_t)t0 * ROWF4;

    #pragma unroll 4
    for (int k = 0; k < NITER; k++) {
        int idx    = tid + k * TPB;
        int slab   = idx / ROWF4;          // const-div -> mul/shift
        int inslab = idx - slab * ROWF4;
        float s    = (inslab < TOPF4) ? s_sh[slab] : 0.f;
        __stcs(base + idx, make_float4(s, s, s, s));
    }
}

extern "C" void kernel_launch(void* const* d_in, const int* in_sizes, int n_in,
                              void* d_out, int out_size)
{
    const float* hid = (const float*)d_in[0];   // (1, 8192, 400)
    const float* W   = (const float*)d_in[1];   // (3, 400)
    const float* b   = (const float*)d_in[2];   // (3,)
    const float* D   = (const float*)d_in[3];   // (1, 400)
    float* out = (float*)d_out;                 // (1, 8192, 32, 400)

    stack_kernel<<<SEQ / SPB, TPB>>>(hid, W, b, D, out);
}